// round 7
// baseline (speedup 1.0000x reference)
#include <cuda_runtime.h>

// B=8 batches, N=1,000,000 vertices of 6 floats (pos[3], nrm[3]).
// out pos = T[:3,:4] @ [pos,1]   (bottom row exactly [0,0,0,1] -> divide elided)
// out nrm = normalize(T[:3,:3] @ nrm), norm clamped at 1e-8
//           == n * min(rsqrt(|n|^2), 1e8)  (bit-compatible clamp, incl. |n|=0)
// batch_indices input is unused by the reference.
//
// Latency-bound per R5 ncu (DRAM 66%, L1 64%, issue 26%, occ 60%): keep the
// proven 2-verts/thread 3xfloat4 shape, raise occupancy to 64 warps/SM by
// capping registers at 32 (__launch_bounds__(256, 8)).

static constexpr int B_ = 8;
static constexpr int N_ = 1000000;
static constexpr int PAIRS_PER_BATCH = N_ / 2;                 // 500,000
static constexpr int THREADS = 256;
static constexpr int BLOCKS_PER_BATCH = (PAIRS_PER_BATCH + THREADS - 1) / THREADS;  // 1954
static constexpr int TOTAL_BLOCKS = BLOCKS_PER_BATCH * B_;      // 15632

__device__ __forceinline__ void xform_one(
    float px, float py, float pz, float nx, float ny, float nz,
    float t00, float t01, float t02, float t03,
    float t10, float t11, float t12, float t13,
    float t20, float t21, float t22, float t23,
    float& ox, float& oy, float& oz, float& mx, float& my, float& mz)
{
    ox = fmaf(t00, px, fmaf(t01, py, fmaf(t02, pz, t03)));
    oy = fmaf(t10, px, fmaf(t11, py, fmaf(t12, pz, t13)));
    oz = fmaf(t20, px, fmaf(t21, py, fmaf(t22, pz, t23)));

    float ux = fmaf(t00, nx, fmaf(t01, ny, t02 * nz));
    float uy = fmaf(t10, nx, fmaf(t11, ny, t12 * nz));
    float uz = fmaf(t20, nx, fmaf(t21, ny, t22 * nz));
    float s  = fmaf(ux, ux, fmaf(uy, uy, uz * uz));
    // l = max(sqrt(s), 1e-8); inv = 1/l  ===  inv = min(rsqrt(s), 1e8)
    float inv = fminf(rsqrtf(s), 1e8f);
    mx = ux * inv;
    my = uy * inv;
    mz = uz * inv;
}

__global__ void __launch_bounds__(THREADS, 8)
vertex_xform_kernel(const float* __restrict__ verts,
                    const float* __restrict__ transforms,
                    float* __restrict__ out)
{
    __shared__ float sT[12];

    const int b      = blockIdx.x / BLOCKS_PER_BATCH;   // block-uniform
    const int blk_in = blockIdx.x - b * BLOCKS_PER_BATCH;

    if (threadIdx.x < 12)
        sT[threadIdx.x] = transforms[b * 16 + threadIdx.x];
    __syncthreads();

    const int p = blk_in * THREADS + threadIdx.x;       // pair index within batch
    if (p >= PAIRS_PER_BATCH) return;

    const float t00 = sT[0],  t01 = sT[1],  t02 = sT[2],  t03 = sT[3];
    const float t10 = sT[4],  t11 = sT[5],  t12 = sT[6],  t13 = sT[7];
    const float t20 = sT[8],  t21 = sT[9],  t22 = sT[10], t23 = sT[11];

    // 2 vertices = 48 bytes = 3 x float4 (16B aligned: 48*p % 16 == 0)
    const size_t base = (size_t)b * ((size_t)N_ * 6 / 4) + (size_t)p * 3;   // float4 units
    const float4* __restrict__ vin = reinterpret_cast<const float4*>(verts) + base;

    float4 a0 = vin[0];
    float4 a1 = vin[1];
    float4 a2 = vin[2];

    // v0: pos a0.xyz           nrm (a0.w, a1.x, a1.y)
    // v1: pos (a1.z,a1.w,a2.x) nrm a2.yzw
    float o0x,o0y,o0z,m0x,m0y,m0z;
    float o1x,o1y,o1z,m1x,m1y,m1z;

    xform_one(a0.x,a0.y,a0.z, a0.w,a1.x,a1.y,
              t00,t01,t02,t03,t10,t11,t12,t13,t20,t21,t22,t23,
              o0x,o0y,o0z,m0x,m0y,m0z);
    xform_one(a1.z,a1.w,a2.x, a2.y,a2.z,a2.w,
              t00,t01,t02,t03,t10,t11,t12,t13,t20,t21,t22,t23,
              o1x,o1y,o1z,m1x,m1y,m1z);

    float4* __restrict__ vout = reinterpret_cast<float4*>(out) + base;
    vout[0] = make_float4(o0x, o0y, o0z, m0x);
    vout[1] = make_float4(m0y, m0z, o1x, o1y);
    vout[2] = make_float4(o1z, m1x, m1y, m1z);
}

extern "C" void kernel_launch(void* const* d_in, const int* in_sizes, int n_in,
                              void* d_out, int out_size)
{
    const float* verts      = (const float*)d_in[0];  // (B, N, 6) float32
    // d_in[1] = batch_indices (unused)
    const float* transforms = (const float*)d_in[2];  // (B, 4, 4) float32
    float* out = (float*)d_out;                       // (B, N, 6) float32

    vertex_xform_kernel<<<TOTAL_BLOCKS, THREADS>>>(verts, transforms, out);
}

// round 8
// speedup vs baseline: 1.0333x; 1.0333x over previous
#include <cuda_runtime.h>

// B=8, N=1,000,000 vertices x 6 floats (pos, nrm), AoS.
// out pos = T[:3,:4] @ [pos,1]  (bottom row exactly [0,0,0,1] -> divide elided)
// out nrm = n_t * min(rsqrt(|n_t|^2), 1e8)   (== normalize with 1e-8 clamp)
// batch_indices unused by the reference.
//
// R6 ncu: HBM pinned at 5.4TB/s regardless of occupancy -> L1tex wavefront
// (sector-replay) bound from 48B-stride AoS float4 access (12 lines/LDG).
// Fix: smem transpose so every LDG/STG is fully coalesced (4 lines/instr).
//   fill  : thread t <- gmem f4 [base+t, +256, +512]   (coalesced)
//   work  : thread t <-> smem f4 [3t, 3t+1, 3t+2]      (48B-stride, conflict-free)
//   drain : thread t -> gmem f4 [base+t, +256, +512]   (coalesced)

static constexpr int N_PER_BATCH = 1000000;
static constexpr int THREADS = 256;
static constexpr int F4_PER_BLOCK = 3 * THREADS;                 // 768 f4 = 512 verts
static constexpr int VERTS_PER_BLOCK = 2 * THREADS;              // 512
static constexpr long long TOTAL_F4 = 12000000LL;                // 8 * 1e6 * 6 / 4
static constexpr int TOTAL_BLOCKS = (int)(TOTAL_F4 / F4_PER_BLOCK);  // 15625 exact

__device__ __forceinline__ void xform_one(
    float px, float py, float pz, float nx, float ny, float nz,
    float t00, float t01, float t02, float t03,
    float t10, float t11, float t12, float t13,
    float t20, float t21, float t22, float t23,
    float& ox, float& oy, float& oz, float& mx, float& my, float& mz)
{
    ox = fmaf(t00, px, fmaf(t01, py, fmaf(t02, pz, t03)));
    oy = fmaf(t10, px, fmaf(t11, py, fmaf(t12, pz, t13)));
    oz = fmaf(t20, px, fmaf(t21, py, fmaf(t22, pz, t23)));

    float ux = fmaf(t00, nx, fmaf(t01, ny, t02 * nz));
    float uy = fmaf(t10, nx, fmaf(t11, ny, t12 * nz));
    float uz = fmaf(t20, nx, fmaf(t21, ny, t22 * nz));
    float s  = fmaf(ux, ux, fmaf(uy, uy, uz * uz));
    // max(sqrt(s),1e-8) then reciprocal  ==  min(rsqrt(s), 1e8)
    float inv = fminf(rsqrtf(s), 1e8f);
    mx = ux * inv;
    my = uy * inv;
    mz = uz * inv;
}

__global__ void __launch_bounds__(THREADS, 8)
vertex_xform_kernel(const float* __restrict__ verts,
                    const float* __restrict__ transforms,
                    float* __restrict__ out)
{
    __shared__ float4 sbuf[F4_PER_BLOCK];   // 12288 B

    const int t = threadIdx.x;
    const long long blockF4 = (long long)blockIdx.x * F4_PER_BLOCK;

    // ---- Phase 1: coalesced fill (each LDG.128: 32 contiguous lanes = 4 lines)
    const float4* __restrict__ gin = reinterpret_cast<const float4*>(verts) + blockF4;
    sbuf[t]               = gin[t];
    sbuf[t + THREADS]     = gin[t + THREADS];
    sbuf[t + 2 * THREADS] = gin[t + 2 * THREADS];
    __syncthreads();

    // ---- Phase 2: per-thread exact 2 vertices from smem (conflict-free LDS.128)
    float4 a0 = sbuf[3 * t + 0];
    float4 a1 = sbuf[3 * t + 1];
    float4 a2 = sbuf[3 * t + 2];

    // vertex ids: v0 = block*512 + 2t, v1 = v0+1; pair never straddles a batch
    const int v0 = blockIdx.x * VERTS_PER_BLOCK + 2 * t;
    const int b  = v0 / N_PER_BATCH;

    const float* T = transforms + b * 16;
    const float t00 = __ldg(T + 0),  t01 = __ldg(T + 1),  t02 = __ldg(T + 2),  t03 = __ldg(T + 3);
    const float t10 = __ldg(T + 4),  t11 = __ldg(T + 5),  t12 = __ldg(T + 6),  t13 = __ldg(T + 7);
    const float t20 = __ldg(T + 8),  t21 = __ldg(T + 9),  t22 = __ldg(T + 10), t23 = __ldg(T + 11);

    // v0: pos a0.xyz           nrm (a0.w, a1.x, a1.y)
    // v1: pos (a1.z,a1.w,a2.x) nrm a2.yzw
    float o0x,o0y,o0z,m0x,m0y,m0z;
    float o1x,o1y,o1z,m1x,m1y,m1z;

    xform_one(a0.x,a0.y,a0.z, a0.w,a1.x,a1.y,
              t00,t01,t02,t03,t10,t11,t12,t13,t20,t21,t22,t23,
              o0x,o0y,o0z,m0x,m0y,m0z);
    xform_one(a1.z,a1.w,a2.x, a2.y,a2.z,a2.w,
              t00,t01,t02,t03,t10,t11,t12,t13,t20,t21,t22,t23,
              o1x,o1y,o1z,m1x,m1y,m1z);

    // write back in place (own 3 slots only -> no cross-thread hazard)
    sbuf[3 * t + 0] = make_float4(o0x, o0y, o0z, m0x);
    sbuf[3 * t + 1] = make_float4(m0y, m0z, o1x, o1y);
    sbuf[3 * t + 2] = make_float4(o1z, m1x, m1y, m1z);
    __syncthreads();

    // ---- Phase 3: coalesced drain
    float4* __restrict__ gout = reinterpret_cast<float4*>(out) + blockF4;
    gout[t]               = sbuf[t];
    gout[t + THREADS]     = sbuf[t + THREADS];
    gout[t + 2 * THREADS] = sbuf[t + 2 * THREADS];
}

extern "C" void kernel_launch(void* const* d_in, const int* in_sizes, int n_in,
                              void* d_out, int out_size)
{
    const float* verts      = (const float*)d_in[0];  // (B, N, 6) float32
    // d_in[1] = batch_indices (unused)
    const float* transforms = (const float*)d_in[2];  // (B, 4, 4) float32
    float* out = (float*)d_out;                       // (B, N, 6) float32

    vertex_xform_kernel<<<TOTAL_BLOCKS, THREADS>>>(verts, transforms, out);
}